// round 4
// baseline (speedup 1.0000x reference)
#include <cuda_runtime.h>
#include <math.h>

#define BATCH 16
#define SEQ   4096
#define CH    512
#define DIM   64

// Scratch (allocation-free rule: __device__ globals)
__device__ float g_q[(size_t)BATCH * SEQ * DIM];   // 16.8 MB
__device__ float g_k[(size_t)BATCH * SEQ * DIM];   // 16.8 MB
__device__ float g_v[(size_t)BATCH * SEQ * CH];    // 134 MB

// ---------------------------------------------------------------------------
// Generic row-major SGEMM with bias epilogue: C[M,N] = A[M,K] * B[K,N] + bias
// ---------------------------------------------------------------------------
template<int BM, int BN, int BK, int TM, int TN>
__global__ void __launch_bounds__((BM / TM) * (BN / TN))
sgemm_nn_bias(const float* __restrict__ A, const float* __restrict__ B,
              const float* __restrict__ bias, float* __restrict__ C,
              int M, int N, int K)
{
    constexpr int NT = (BM / TM) * (BN / TN);
    __shared__ float As[BK][BM];
    __shared__ float Bs[BK][BN];

    const int tid  = threadIdx.x;
    const int tCol = tid % (BN / TN);
    const int tRow = tid / (BN / TN);
    const int rowBase = blockIdx.y * BM;
    const int colBase = blockIdx.x * BN;

    float acc[TM][TN];
    #pragma unroll
    for (int i = 0; i < TM; i++)
        #pragma unroll
        for (int j = 0; j < TN; j++) acc[i][j] = 0.0f;

    constexpr int AIT = (BM * BK) / (4 * NT);
    constexpr int BIT = (BK * BN) / (4 * NT);

    for (int k0 = 0; k0 < K; k0 += BK) {
        #pragma unroll
        for (int it = 0; it < AIT; it++) {
            int idx = tid + it * NT;
            int r = idx / (BK / 4);
            int c = (idx % (BK / 4)) * 4;
            float4 t = *reinterpret_cast<const float4*>(
                &A[(size_t)(rowBase + r) * K + k0 + c]);
            As[c + 0][r] = t.x; As[c + 1][r] = t.y;
            As[c + 2][r] = t.z; As[c + 3][r] = t.w;
        }
        #pragma unroll
        for (int it = 0; it < BIT; it++) {
            int idx = tid + it * NT;
            int r = idx / (BN / 4);
            int c = (idx % (BN / 4)) * 4;
            *reinterpret_cast<float4*>(&Bs[r][c]) =
                *reinterpret_cast<const float4*>(
                    &B[(size_t)(k0 + r) * N + colBase + c]);
        }
        __syncthreads();

        #pragma unroll
        for (int kk = 0; kk < BK; kk++) {
            float rA[TM], rB[TN];
            #pragma unroll
            for (int i = 0; i < TM; i++) rA[i] = As[kk][tRow * TM + i];
            #pragma unroll
            for (int j = 0; j < TN; j++) rB[j] = Bs[kk][tCol * TN + j];
            #pragma unroll
            for (int i = 0; i < TM; i++)
                #pragma unroll
                for (int j = 0; j < TN; j++)
                    acc[i][j] += rA[i] * rB[j];
        }
        __syncthreads();
    }

    #pragma unroll
    for (int i = 0; i < TM; i++) {
        const int row = rowBase + tRow * TM + i;
        #pragma unroll
        for (int j = 0; j < TN; j += 4) {
            const int col = colBase + tCol * TN + j;
            float4 o;
            o.x = acc[i][j + 0] + bias[col + 0];
            o.y = acc[i][j + 1] + bias[col + 1];
            o.z = acc[i][j + 2] + bias[col + 2];
            o.w = acc[i][j + 3] + bias[col + 3];
            *reinterpret_cast<float4*>(&C[(size_t)row * N + col]) = o;
        }
    }
}

// ---------------------------------------------------------------------------
// Batched energy: E[b,n,m] = sum_d Q[b,n,d] * K[b,m,d]   (A * B^T, both [SEQ,DIM])
// ---------------------------------------------------------------------------
template<int BM, int BN, int BK, int TM, int TN>
__global__ void __launch_bounds__((BM / TM) * (BN / TN))
sgemm_nt_energy(const float* __restrict__ Q, const float* __restrict__ Kmat,
                float* __restrict__ E)
{
    constexpr int NT = (BM / TM) * (BN / TN);
    __shared__ float As[BK][BM];
    __shared__ float Bs[BK][BN];

    const int b = blockIdx.z;
    const float* Ab = Q    + (size_t)b * SEQ * DIM;
    const float* Bb = Kmat + (size_t)b * SEQ * DIM;
    float*       Cb = E    + (size_t)b * SEQ * SEQ;

    const int tid  = threadIdx.x;
    const int tCol = tid % (BN / TN);
    const int tRow = tid / (BN / TN);
    const int rowBase = blockIdx.y * BM;
    const int colBase = blockIdx.x * BN;

    float acc[TM][TN];
    #pragma unroll
    for (int i = 0; i < TM; i++)
        #pragma unroll
        for (int j = 0; j < TN; j++) acc[i][j] = 0.0f;

    constexpr int AIT = (BM * BK) / (4 * NT);
    constexpr int BIT = (BN * BK) / (4 * NT);

    for (int k0 = 0; k0 < DIM; k0 += BK) {
        #pragma unroll
        for (int it = 0; it < AIT; it++) {
            int idx = tid + it * NT;
            int r = idx / (BK / 4);
            int c = (idx % (BK / 4)) * 4;
            float4 t = *reinterpret_cast<const float4*>(
                &Ab[(size_t)(rowBase + r) * DIM + k0 + c]);
            As[c + 0][r] = t.x; As[c + 1][r] = t.y;
            As[c + 2][r] = t.z; As[c + 3][r] = t.w;
        }
        #pragma unroll
        for (int it = 0; it < BIT; it++) {
            int idx = tid + it * NT;
            int r = idx / (BK / 4);              // key row within tile
            int c = (idx % (BK / 4)) * 4;        // d offset
            float4 t = *reinterpret_cast<const float4*>(
                &Bb[(size_t)(colBase + r) * DIM + k0 + c]);
            Bs[c + 0][r] = t.x; Bs[c + 1][r] = t.y;
            Bs[c + 2][r] = t.z; Bs[c + 3][r] = t.w;
        }
        __syncthreads();

        #pragma unroll
        for (int kk = 0; kk < BK; kk++) {
            float rA[TM], rB[TN];
            #pragma unroll
            for (int i = 0; i < TM; i++) rA[i] = As[kk][tRow * TM + i];
            #pragma unroll
            for (int j = 0; j < TN; j++) rB[j] = Bs[kk][tCol * TN + j];
            #pragma unroll
            for (int i = 0; i < TM; i++)
                #pragma unroll
                for (int j = 0; j < TN; j++)
                    acc[i][j] += rA[i] * rB[j];
        }
        __syncthreads();
    }

    #pragma unroll
    for (int i = 0; i < TM; i++) {
        const int row = rowBase + tRow * TM + i;
        #pragma unroll
        for (int j = 0; j < TN; j += 4) {
            const int col = colBase + tCol * TN + j;
            float4 o;
            o.x = acc[i][j + 0]; o.y = acc[i][j + 1];
            o.z = acc[i][j + 2]; o.w = acc[i][j + 3];
            *reinterpret_cast<float4*>(&Cb[(size_t)row * SEQ + col]) = o;
        }
    }
}

// ---------------------------------------------------------------------------
// In-place row softmax over SEQ=4096 elements. One block per row.
// ---------------------------------------------------------------------------
__global__ void __launch_bounds__(256)
softmax_rows_kernel(float* __restrict__ att)
{
    const int tid = threadIdx.x;
    float* __restrict__ p = att + (size_t)blockIdx.x * SEQ;
    __shared__ float buf[SEQ];
    __shared__ float red[8];

    float4* __restrict__ p4 = reinterpret_cast<float4*>(p);
    float4* b4 = reinterpret_cast<float4*>(buf);

    float lmax = -3.402823466e38f;
    #pragma unroll
    for (int it = 0; it < SEQ / 4 / 256; ++it) {
        int i = tid + it * 256;
        float4 t = p4[i];
        b4[i] = t;
        lmax = fmaxf(lmax, fmaxf(fmaxf(t.x, t.y), fmaxf(t.z, t.w)));
    }
    #pragma unroll
    for (int o = 16; o > 0; o >>= 1)
        lmax = fmaxf(lmax, __shfl_xor_sync(0xffffffffu, lmax, o));
    if ((tid & 31) == 0) red[tid >> 5] = lmax;
    __syncthreads();
    float m = red[0];
    #pragma unroll
    for (int i = 1; i < 8; i++) m = fmaxf(m, red[i]);
    __syncthreads();

    float lsum = 0.0f;
    #pragma unroll
    for (int it = 0; it < SEQ / 4 / 256; ++it) {
        int i = tid + it * 256;
        float4 t = b4[i];
        t.x = __expf(t.x - m); t.y = __expf(t.y - m);
        t.z = __expf(t.z - m); t.w = __expf(t.w - m);
        b4[i] = t;
        lsum += (t.x + t.y) + (t.z + t.w);
    }
    #pragma unroll
    for (int o = 16; o > 0; o >>= 1)
        lsum += __shfl_xor_sync(0xffffffffu, lsum, o);
    if ((tid & 31) == 0) red[tid >> 5] = lsum;
    __syncthreads();
    float s = red[0];
    #pragma unroll
    for (int i = 1; i < 8; i++) s += red[i];
    const float inv = 1.0f / s;

    #pragma unroll
    for (int it = 0; it < SEQ / 4 / 256; ++it) {
        int i = tid + it * 256;
        float4 t = b4[i];
        t.x *= inv; t.y *= inv; t.z *= inv; t.w *= inv;
        p4[i] = t;
    }
}

// ---------------------------------------------------------------------------
// Batched PV: Out[b,n,c] = gamma * sum_m P[b,n,m] * V[b,m,c] + X[b,n,c]
// ---------------------------------------------------------------------------
template<int BM, int BN, int BK, int TM, int TN>
__global__ void __launch_bounds__((BM / TM) * (BN / TN))
sgemm_pv(const float* __restrict__ P, const float* __restrict__ V,
         const float* __restrict__ X, const float* __restrict__ gamma,
         float* __restrict__ Out)
{
    constexpr int NT = (BM / TM) * (BN / TN);
    __shared__ float As[BK][BM];
    __shared__ float Bs[BK][BN];

    const int b = blockIdx.z;
    const float* Ab = P + (size_t)b * SEQ * SEQ;
    const float* Bb = V + (size_t)b * SEQ * CH;
    const float* Xb = X + (size_t)b * SEQ * CH;
    float*       Cb = Out + (size_t)b * SEQ * CH;

    const int tid  = threadIdx.x;
    const int tCol = tid % (BN / TN);
    const int tRow = tid / (BN / TN);
    const int rowBase = blockIdx.y * BM;
    const int colBase = blockIdx.x * BN;

    float acc[TM][TN];
    #pragma unroll
    for (int i = 0; i < TM; i++)
        #pragma unroll
        for (int j = 0; j < TN; j++) acc[i][j] = 0.0f;

    constexpr int AIT = (BM * BK) / (4 * NT);
    constexpr int BIT = (BK * BN) / (4 * NT);

    for (int k0 = 0; k0 < SEQ; k0 += BK) {
        #pragma unroll
        for (int it = 0; it < AIT; it++) {
            int idx = tid + it * NT;
            int r = idx / (BK / 4);
            int c = (idx % (BK / 4)) * 4;
            float4 t = *reinterpret_cast<const float4*>(
                &Ab[(size_t)(rowBase + r) * SEQ + k0 + c]);
            As[c + 0][r] = t.x; As[c + 1][r] = t.y;
            As[c + 2][r] = t.z; As[c + 3][r] = t.w;
        }
        #pragma unroll
        for (int it = 0; it < BIT; it++) {
            int idx = tid + it * NT;
            int r = idx / (BN / 4);
            int c = (idx % (BN / 4)) * 4;
            *reinterpret_cast<float4*>(&Bs[r][c]) =
                *reinterpret_cast<const float4*>(
                    &Bb[(size_t)(k0 + r) * CH + colBase + c]);
        }
        __syncthreads();

        #pragma unroll
        for (int kk = 0; kk < BK; kk++) {
            float rA[TM], rB[TN];
            #pragma unroll
            for (int i = 0; i < TM; i++) rA[i] = As[kk][tRow * TM + i];
            #pragma unroll
            for (int j = 0; j < TN; j++) rB[j] = Bs[kk][tCol * TN + j];
            #pragma unroll
            for (int i = 0; i < TM; i++)
                #pragma unroll
                for (int j = 0; j < TN; j++)
                    acc[i][j] += rA[i] * rB[j];
        }
        __syncthreads();
    }

    const float g = gamma[0];
    #pragma unroll
    for (int i = 0; i < TM; i++) {
        const int row = rowBase + tRow * TM + i;
        #pragma unroll
        for (int j = 0; j < TN; j += 4) {
            const int col = colBase + tCol * TN + j;
            const float4 xr = *reinterpret_cast<const float4*>(
                &Xb[(size_t)row * CH + col]);
            float4 o;
            o.x = fmaf(g, acc[i][j + 0], xr.x);
            o.y = fmaf(g, acc[i][j + 1], xr.y);
            o.z = fmaf(g, acc[i][j + 2], xr.z);
            o.w = fmaf(g, acc[i][j + 3], xr.w);
            *reinterpret_cast<float4*>(&Cb[(size_t)row * CH + col]) = o;
        }
    }
}

// ---------------------------------------------------------------------------
extern "C" void kernel_launch(void* const* d_in, const int* in_sizes, int n_in,
                              void* d_out, int out_size)
{
    const float* x     = (const float*)d_in[0];
    const float* Wq    = (const float*)d_in[1];
    const float* bq    = (const float*)d_in[2];
    const float* Wk    = (const float*)d_in[3];
    const float* bk    = (const float*)d_in[4];
    const float* Wv    = (const float*)d_in[5];
    const float* bv    = (const float*)d_in[6];
    const float* gamma = (const float*)d_in[7];

    float* out = (float*)d_out;                           // [B, N, C]
    float* att = out + (size_t)BATCH * SEQ * CH;          // [B, N, N]

    float *pq, *pk, *pv;
    cudaGetSymbolAddress((void**)&pq, g_q);
    cudaGetSymbolAddress((void**)&pk, g_k);
    cudaGetSymbolAddress((void**)&pv, g_v);

    const int M = BATCH * SEQ;   // 65536

    // Projections: q, k (N=64), v (N=512)
    sgemm_nn_bias<128, 64, 16, 8, 8>
        <<<dim3(1, M / 128), 128>>>(x, Wq, bq, pq, M, DIM, CH);
    sgemm_nn_bias<128, 64, 16, 8, 8>
        <<<dim3(1, M / 128), 128>>>(x, Wk, bk, pk, M, DIM, CH);
    sgemm_nn_bias<128, 128, 16, 8, 8>
        <<<dim3(CH / 128, M / 128), 256>>>(x, Wv, bv, pv, M, CH, CH);

    // Raw energy -> attention region of d_out
    sgemm_nt_energy<128, 128, 16, 8, 8>
        <<<dim3(SEQ / 128, SEQ / 128, BATCH), 256>>>(pq, pk, att);

    // In-place softmax over keys
    softmax_rows_kernel<<<BATCH * SEQ, 256>>>(att);

    // out = gamma * (attn @ v) + x
    sgemm_pv<128, 128, 16, 8, 8>
        <<<dim3(CH / 128, SEQ / 128, BATCH), 256>>>(att, pv, x, gamma, out);
}

// round 10
// speedup vs baseline: 2.9209x; 2.9209x over previous
#include <cuda_runtime.h>
#include <math.h>
#include <stdint.h>

#define BATCH 16
#define SEQ   4096
#define CH    512
#define DIM   64

// Scratch (allocation-free rule: __device__ globals)
__device__ float g_q [(size_t)BATCH * SEQ * DIM];   // 16.8 MB
__device__ float g_k [(size_t)BATCH * SEQ * DIM];   // 16.8 MB
__device__ float g_v [(size_t)BATCH * SEQ * CH];    // 134 MB  [B, SEQ, CH]

// ===========================================================================
// Helpers
// ===========================================================================
__device__ __forceinline__ float tf32r(float x) {   // round-to-nearest tf32
    uint32_t u;
    asm("cvt.rna.tf32.f32 %0, %1;" : "=r"(u) : "f"(x));
    return __uint_as_float(u);
}

// D += A * B, one m16n8k4 tf32 warp MMA.
// A: 2 regs {(g,t),(g+8,t)}; B: 1 reg (t,g); D: 4 regs {(g,2t),(g,2t+1),(g+8,2t),(g+8,2t+1)}
__device__ __forceinline__ void mma_k4(float* d, const float* a, float b) {
    asm volatile(
        "mma.sync.aligned.m16n8k4.row.col.f32.tf32.tf32.f32 "
        "{%0,%1,%2,%3}, {%4,%5}, {%6}, {%0,%1,%2,%3};\n"
        : "+f"(d[0]), "+f"(d[1]), "+f"(d[2]), "+f"(d[3])
        : "r"(__float_as_uint(a[0])), "r"(__float_as_uint(a[1])),
          "r"(__float_as_uint(b)));
}

// ===========================================================================
// PV kernel (warp-level tf32 tensor cores):
//   Out[b,m,c] = gamma * sum_k P[b,m,k] * V[b,k,c] + X[b,m,c]
// Block tile 128x128, BK=32, 8 warps (4x2), warp tile 32x64.
// ===========================================================================
#define PVB_K 32
#define PS_LD 36    // 32 + 4 pad: A-frag LDS bank = (4m + k) % 32, conflict-free
#define VS_LD 136   // 128 + 8 pad: B-frag LDS bank = (8t + g) % 32, conflict-free

__global__ void __launch_bounds__(256, 2)
pv_mma_kernel(const float* __restrict__ P, const float* __restrict__ V,
              const float* __restrict__ X, const float* __restrict__ gamma,
              float* __restrict__ Out)
{
    __shared__ float Ps[128][PS_LD];   // [m][k]
    __shared__ float Vs[PVB_K][VS_LD]; // [k][c]

    const int tid  = threadIdx.x;
    const int lane = tid & 31;
    const int wid  = tid >> 5;
    const int wm   = wid & 3;          // warp row 0..3 -> 32 rows each
    const int wn   = wid >> 2;         // warp col 0..1 -> 64 cols each
    const int g    = lane >> 2;        // groupID
    const int t    = lane & 3;         // threadID_in_group

    const int b  = blockIdx.z;
    const int m0 = blockIdx.y * 128;
    const int c0 = blockIdx.x * 128;

    const float* __restrict__ Pb = P + (size_t)b * SEQ * SEQ;
    const float* __restrict__ Vb = V + (size_t)b * SEQ * CH;

    float acc[2][8][4];
    #pragma unroll
    for (int mt = 0; mt < 2; mt++)
        #pragma unroll
        for (int nt = 0; nt < 8; nt++)
            #pragma unroll
            for (int i = 0; i < 4; i++) acc[mt][nt][i] = 0.0f;

    for (int k0 = 0; k0 < SEQ; k0 += PVB_K) {
        // load P tile [128m x 32k] (float4 along k, coalesced)
        #pragma unroll
        for (int i = 0; i < 4; i++) {
            const int m  = (tid >> 3) + i * 32;
            const int kk = (tid & 7) * 4;
            float4 p = *reinterpret_cast<const float4*>(
                &Pb[(size_t)(m0 + m) * SEQ + k0 + kk]);
            Ps[m][kk + 0] = tf32r(p.x);
            Ps[m][kk + 1] = tf32r(p.y);
            Ps[m][kk + 2] = tf32r(p.z);
            Ps[m][kk + 3] = tf32r(p.w);
        }
        // load V tile [32k x 128c] (float4 along c, coalesced, natural layout)
        #pragma unroll
        for (int i = 0; i < 4; i++) {
            const int idx = tid + i * 256;
            const int k   = idx >> 5;
            const int c   = (idx & 31) * 4;
            float4 v = *reinterpret_cast<const float4*>(
                &Vb[(size_t)(k0 + k) * CH + c0 + c]);
            Vs[k][c + 0] = tf32r(v.x);
            Vs[k][c + 1] = tf32r(v.y);
            Vs[k][c + 2] = tf32r(v.z);
            Vs[k][c + 3] = tf32r(v.w);
        }
        __syncthreads();

        #pragma unroll
        for (int ks = 0; ks < PVB_K / 4; ks++) {
            const int kk = ks * 4 + t;
            float a[2][2];
            #pragma unroll
            for (int mt = 0; mt < 2; mt++) {
                const int r = wm * 32 + mt * 16 + g;
                a[mt][0] = Ps[r][kk];
                a[mt][1] = Ps[r + 8][kk];
            }
            float bf[8];
            #pragma unroll
            for (int nt = 0; nt < 8; nt++)
                bf[nt] = Vs[kk][wn * 64 + nt * 8 + g];
            #pragma unroll
            for (int mt = 0; mt < 2; mt++)
                #pragma unroll
                for (int nt = 0; nt < 8; nt++)
                    mma_k4(acc[mt][nt], a[mt], bf[nt]);
        }
        __syncthreads();
    }

    // epilogue: out = gamma * acc + x
    const float gm = gamma[0];
    const float* __restrict__ Xb = X   + (size_t)b * SEQ * CH;
    float* __restrict__       Ob = Out + (size_t)b * SEQ * CH;

    #pragma unroll
    for (int mt = 0; mt < 2; mt++) {
        const int r0 = m0 + wm * 32 + mt * 16 + g;
        #pragma unroll
        for (int nt = 0; nt < 8; nt++) {
            const int c = c0 + wn * 64 + nt * 8 + 2 * t;
            const float2 x0 = *reinterpret_cast<const float2*>(
                &Xb[(size_t)r0 * CH + c]);
            const float2 x1 = *reinterpret_cast<const float2*>(
                &Xb[(size_t)(r0 + 8) * CH + c]);
            float2 o0, o1;
            o0.x = fmaf(gm, acc[mt][nt][0], x0.x);
            o0.y = fmaf(gm, acc[mt][nt][1], x0.y);
            o1.x = fmaf(gm, acc[mt][nt][2], x1.x);
            o1.y = fmaf(gm, acc[mt][nt][3], x1.y);
            *reinterpret_cast<float2*>(&Ob[(size_t)r0 * CH + c]) = o0;
            *reinterpret_cast<float2*>(&Ob[(size_t)(r0 + 8) * CH + c]) = o1;
        }
    }
}

// ===========================================================================
// SIMT SGEMMs (verbatim from the passing round-4 kernel)
// ===========================================================================
template<int BM, int BN, int BK, int TM, int TN>
__global__ void __launch_bounds__((BM / TM) * (BN / TN))
sgemm_nn_bias(const float* __restrict__ A, const float* __restrict__ B,
              const float* __restrict__ bias, float* __restrict__ C,
              int M, int N, int K)
{
    constexpr int NT = (BM / TM) * (BN / TN);
    __shared__ float As[BK][BM];
    __shared__ float Bs[BK][BN];

    const int tid  = threadIdx.x;
    const int tCol = tid % (BN / TN);
    const int tRow = tid / (BN / TN);
    const int rowBase = blockIdx.y * BM;
    const int colBase = blockIdx.x * BN;

    float acc[TM][TN];
    #pragma unroll
    for (int i = 0; i < TM; i++)
        #pragma unroll
        for (int j = 0; j < TN; j++) acc[i][j] = 0.0f;

    constexpr int AIT = (BM * BK) / (4 * NT);
    constexpr int BIT = (BK * BN) / (4 * NT);

    for (int k0 = 0; k0 < K; k0 += BK) {
        #pragma unroll
        for (int it = 0; it < AIT; it++) {
            int idx = tid + it * NT;
            int r = idx / (BK / 4);
            int c = (idx % (BK / 4)) * 4;
            float4 t = *reinterpret_cast<const float4*>(
                &A[(size_t)(rowBase + r) * K + k0 + c]);
            As[c + 0][r] = t.x; As[c + 1][r] = t.y;
            As[c + 2][r] = t.z; As[c + 3][r] = t.w;
        }
        #pragma unroll
        for (int it = 0; it < BIT; it++) {
            int idx = tid + it * NT;
            int r = idx / (BN / 4);
            int c = (idx % (BN / 4)) * 4;
            *reinterpret_cast<float4*>(&Bs[r][c]) =
                *reinterpret_cast<const float4*>(
                    &B[(size_t)(k0 + r) * N + colBase + c]);
        }
        __syncthreads();

        #pragma unroll
        for (int kk = 0; kk < BK; kk++) {
            float rA[TM], rB[TN];
            #pragma unroll
            for (int i = 0; i < TM; i++) rA[i] = As[kk][tRow * TM + i];
            #pragma unroll
            for (int j = 0; j < TN; j++) rB[j] = Bs[kk][tCol * TN + j];
            #pragma unroll
            for (int i = 0; i < TM; i++)
                #pragma unroll
                for (int j = 0; j < TN; j++)
                    acc[i][j] += rA[i] * rB[j];
        }
        __syncthreads();
    }

    #pragma unroll
    for (int i = 0; i < TM; i++) {
        const int row = rowBase + tRow * TM + i;
        #pragma unroll
        for (int j = 0; j < TN; j += 4) {
            const int col = colBase + tCol * TN + j;
            float4 o;
            o.x = acc[i][j + 0] + bias[col + 0];
            o.y = acc[i][j + 1] + bias[col + 1];
            o.z = acc[i][j + 2] + bias[col + 2];
            o.w = acc[i][j + 3] + bias[col + 3];
            *reinterpret_cast<float4*>(&C[(size_t)row * N + col]) = o;
        }
    }
}

template<int BM, int BN, int BK, int TM, int TN>
__global__ void __launch_bounds__((BM / TM) * (BN / TN))
sgemm_nt_energy(const float* __restrict__ Q, const float* __restrict__ Kmat,
                float* __restrict__ E)
{
    constexpr int NT = (BM / TM) * (BN / TN);
    __shared__ float As[BK][BM];
    __shared__ float Bs[BK][BN];

    const int b = blockIdx.z;
    const float* Ab = Q    + (size_t)b * SEQ * DIM;
    const float* Bb = Kmat + (size_t)b * SEQ * DIM;
    float*       Cb = E    + (size_t)b * SEQ * SEQ;

    const int tid  = threadIdx.x;
    const int tCol = tid % (BN / TN);
    const int tRow = tid / (BN / TN);
    const int rowBase = blockIdx.y * BM;
    const int colBase = blockIdx.x * BN;

    float acc[TM][TN];
    #pragma unroll
    for (int i = 0; i < TM; i++)
        #pragma unroll
        for (int j = 0; j < TN; j++) acc[i][j] = 0.0f;

    constexpr int AIT = (BM * BK) / (4 * NT);
    constexpr int BIT = (BN * BK) / (4 * NT);

    for (int k0 = 0; k0 < DIM; k0 += BK) {
        #pragma unroll
        for (int it = 0; it < AIT; it++) {
            int idx = tid + it * NT;
            int r = idx / (BK / 4);
            int c = (idx % (BK / 4)) * 4;
            float4 t = *reinterpret_cast<const float4*>(
                &Ab[(size_t)(rowBase + r) * DIM + k0 + c]);
            As[c + 0][r] = t.x; As[c + 1][r] = t.y;
            As[c + 2][r] = t.z; As[c + 3][r] = t.w;
        }
        #pragma unroll
        for (int it = 0; it < BIT; it++) {
            int idx = tid + it * NT;
            int r = idx / (BK / 4);
            int c = (idx % (BK / 4)) * 4;
            float4 t = *reinterpret_cast<const float4*>(
                &Bb[(size_t)(colBase + r) * DIM + k0 + c]);
            Bs[c + 0][r] = t.x; Bs[c + 1][r] = t.y;
            Bs[c + 2][r] = t.z; Bs[c + 3][r] = t.w;
        }
        __syncthreads();

        #pragma unroll
        for (int kk = 0; kk < BK; kk++) {
            float rA[TM], rB[TN];
            #pragma unroll
            for (int i = 0; i < TM; i++) rA[i] = As[kk][tRow * TM + i];
            #pragma unroll
            for (int j = 0; j < TN; j++) rB[j] = Bs[kk][tCol * TN + j];
            #pragma unroll
            for (int i = 0; i < TM; i++)
                #pragma unroll
                for (int j = 0; j < TN; j++)
                    acc[i][j] += rA[i] * rB[j];
        }
        __syncthreads();
    }

    #pragma unroll
    for (int i = 0; i < TM; i++) {
        const int row = rowBase + tRow * TM + i;
        #pragma unroll
        for (int j = 0; j < TN; j += 4) {
            const int col = colBase + tCol * TN + j;
            float4 o;
            o.x = acc[i][j + 0]; o.y = acc[i][j + 1];
            o.z = acc[i][j + 2]; o.w = acc[i][j + 3];
            *reinterpret_cast<float4*>(&Cb[(size_t)row * SEQ + col]) = o;
        }
    }
}

__global__ void __launch_bounds__(256)
softmax_rows_kernel(float* __restrict__ att)
{
    const int tid = threadIdx.x;
    float* __restrict__ p = att + (size_t)blockIdx.x * SEQ;
    __shared__ float buf[SEQ];
    __shared__ float red[8];

    float4* __restrict__ p4 = reinterpret_cast<float4*>(p);
    float4* b4 = reinterpret_cast<float4*>(buf);

    float lmax = -3.402823466e38f;
    #pragma unroll
    for (int it = 0; it < SEQ / 4 / 256; ++it) {
        int i = tid + it * 256;
        float4 t = p4[i];
        b4[i] = t;
        lmax = fmaxf(lmax, fmaxf(fmaxf(t.x, t.y), fmaxf(t.z, t.w)));
    }
    #pragma unroll
    for (int o = 16; o > 0; o >>= 1)
        lmax = fmaxf(lmax, __shfl_xor_sync(0xffffffffu, lmax, o));
    if ((tid & 31) == 0) red[tid >> 5] = lmax;
    __syncthreads();
    float m = red[0];
    #pragma unroll
    for (int i = 1; i < 8; i++) m = fmaxf(m, red[i]);
    __syncthreads();

    float lsum = 0.0f;
    #pragma unroll
    for (int it = 0; it < SEQ / 4 / 256; ++it) {
        int i = tid + it * 256;
        float4 t = b4[i];
        t.x = __expf(t.x - m); t.y = __expf(t.y - m);
        t.z = __expf(t.z - m); t.w = __expf(t.w - m);
        b4[i] = t;
        lsum += (t.x + t.y) + (t.z + t.w);
    }
    #pragma unroll
    for (int o = 16; o > 0; o >>= 1)
        lsum += __shfl_xor_sync(0xffffffffu, lsum, o);
    if ((tid & 31) == 0) red[tid >> 5] = lsum;
    __syncthreads();
    float s = red[0];
    #pragma unroll
    for (int i = 1; i < 8; i++) s += red[i];
    const float inv = 1.0f / s;

    #pragma unroll
    for (int it = 0; it < SEQ / 4 / 256; ++it) {
        int i = tid + it * 256;
        float4 t = b4[i];
        t.x *= inv; t.y *= inv; t.z *= inv; t.w *= inv;
        p4[i] = t;
    }
}

// ===========================================================================
extern "C" void kernel_launch(void* const* d_in, const int* in_sizes, int n_in,
                              void* d_out, int out_size)
{
    const float* x     = (const float*)d_in[0];
    const float* Wq    = (const float*)d_in[1];
    const float* bq    = (const float*)d_in[2];
    const float* Wk    = (const float*)d_in[3];
    const float* bk    = (const float*)d_in[4];
    const float* Wv    = (const float*)d_in[5];
    const float* bv    = (const float*)d_in[6];
    const float* gamma = (const float*)d_in[7];

    float* out = (float*)d_out;                           // [B, N, C]
    float* att = out + (size_t)BATCH * SEQ * CH;          // [B, N, N]

    float *pq, *pk, *pv;
    cudaGetSymbolAddress((void**)&pq, g_q);
    cudaGetSymbolAddress((void**)&pk, g_k);
    cudaGetSymbolAddress((void**)&pv, g_v);

    const int M = BATCH * SEQ;   // 65536

    // Projections: q, k (N=64), v (N=512)
    sgemm_nn_bias<128, 64, 16, 8, 8>
        <<<dim3(1, M / 128), 128>>>(x, Wq, bq, pq, M, DIM, CH);
    sgemm_nn_bias<128, 64, 16, 8, 8>
        <<<dim3(1, M / 128), 128>>>(x, Wk, bk, pk, M, DIM, CH);
    sgemm_nn_bias<128, 128, 16, 8, 8>
        <<<dim3(CH / 128, M / 128), 256>>>(x, Wv, bv, pv, M, CH, CH);

    // Raw energy -> attention region of d_out (fp32 exact)
    sgemm_nt_energy<128, 128, 16, 8, 8>
        <<<dim3(SEQ / 128, SEQ / 128, BATCH), 256>>>(pq, pk, att);

    // In-place softmax over keys
    softmax_rows_kernel<<<BATCH * SEQ, 256>>>(att);

    // out = gamma * (attn @ v) + x  — warp-level tf32 tensor cores
    pv_mma_kernel<<<dim3(CH / 128, SEQ / 128, BATCH), 256>>>
        (att, pv, x, gamma, out);
}